// round 7
// baseline (speedup 1.0000x reference)
#include <cuda_runtime.h>
#include <cuda_fp16.h>
#include <cstdint>
#include <cstdio>

// ------------------------------------------------------------------
// Problem constants
// ------------------------------------------------------------------
#define B_DIM   8192
#define IN_DIM  2048
#define H_DIM   2048
#define OUT_DIM 512
#define DEGP1   5
#define K_TOT (IN_DIM * DEGP1)   // 10240 (both layers)
#define BN_EPS 1e-5f
#define WSCALE 256.0f
#define INV_WSCALE (1.0f / 256.0f)

// ------------------------------------------------------------------
// Scratch (device globals; no runtime allocation)
// ------------------------------------------------------------------
__device__ __half g_Aexp[(size_t)B_DIM * K_TOT];    // expanded activations (fp16)
__device__ __half g_W1f [(size_t)H_DIM * K_TOT];    // fused W1 (fp16, x256)
__device__ __half g_W2f [(size_t)OUT_DIM * K_TOT];  // fused W2 (fp16, x256)
__device__ __half g_H1h [(size_t)B_DIM * H_DIM];    // layer-1 pre-BN output (fp16)
__device__ float  g_c1d0[(size_t)H_DIM * IN_DIM];   // s1[h]*c1[i,h,0], transposed
__device__ float  g_c2d0[(size_t)OUT_DIM * H_DIM];
__device__ float  g_bias1[H_DIM];
__device__ float  g_bias2[OUT_DIM];
__device__ float  g_partS [32 * H_DIM];
__device__ float  g_partS2[32 * H_DIM];
__device__ float  g_bnScale[H_DIM];
__device__ float  g_bnShift[H_DIM];

// ------------------------------------------------------------------
// helpers
// ------------------------------------------------------------------
__device__ __forceinline__ void ldsm_x4(uint32_t& r0, uint32_t& r1,
                                        uint32_t& r2, uint32_t& r3, uint32_t addr) {
    asm volatile("ldmatrix.sync.aligned.m8n8.x4.shared.b16 {%0,%1,%2,%3}, [%4];"
                 : "=r"(r0), "=r"(r1), "=r"(r2), "=r"(r3) : "r"(addr));
}

// Single-instruction MUFU.TANH (sm_75+). Abs err ~6e-4 — feeds only the
// polynomial blocks whose total output contribution is ~0.4%, so the induced
// output error is ~2e-5 relative. The exact base block bypasses tanh.
__device__ __forceinline__ float tanh_fast(float x) {
    float r;
    asm("tanh.approx.f32 %0, %1;" : "=f"(r) : "f"(x));
    return r;
}

// ------------------------------------------------------------------
// Coefficient fusion via smem transpose.
// ------------------------------------------------------------------
__global__ void fuse_c_kernel(const float* __restrict__ c,
                              const float* __restrict__ s,
                              __half* __restrict__ Wf,
                              float* __restrict__ cd0,
                              int In, int Hh) {
    __shared__ float sm[160][33];
    const int tid = threadIdx.x;
    const int i0 = blockIdx.x * 32;
    const int h0 = blockIdx.y * 32;

    for (int e = tid; e < 32 * 160; e += 256) {
        int ii  = e / 160;
        int pos = e % 160;
        sm[pos][ii] = c[(size_t)(i0 + ii) * Hh * DEGP1 + (size_t)h0 * DEGP1 + pos];
    }
    __syncthreads();

    const int lane = tid & 31;
    for (int hl = tid >> 5; hl < 32; hl += 8) {
        float sv = s[h0 + hl];
        cd0[(size_t)(h0 + hl) * In + i0 + lane] = sv * sm[hl * DEGP1][lane];
        __half* wrow = Wf + (size_t)(h0 + hl) * (In * DEGP1);
#pragma unroll
        for (int d = 1; d < DEGP1; ++d)
            wrow[d * In + i0 + lane] =
                __float2half_rn(WSCALE * sv * sm[hl * DEGP1 + d][lane]);
    }
}

// W base block (d=0): Wf[row][col] = half(WSCALE * w[row][col])
__global__ void base_w_kernel(const float* __restrict__ w,
                              __half* __restrict__ Wf, int In, long total) {
    long idx = (long)blockIdx.x * blockDim.x + threadIdx.x;
    if (idx >= total) return;
    int row = (int)(idx / In);
    int col = (int)(idx % In);
    Wf[(size_t)row * (In * DEGP1) + col] = __float2half_rn(WSCALE * w[idx]);
}

// bias[o] = b[o] + sum_j staged[o*len + j]
__global__ void bias_reduce_kernel(const float* __restrict__ staged,
                                   const float* __restrict__ b,
                                   float* __restrict__ dst, int len) {
    __shared__ float red[256];
    int o = blockIdx.x;
    const float* src = staged + (size_t)o * len;
    float s = 0.f;
    for (int j = threadIdx.x; j < len; j += 256) s += src[j];
    red[threadIdx.x] = s;
    __syncthreads();
    for (int st = 128; st > 0; st >>= 1) {
        if (threadIdx.x < st) red[threadIdx.x] += red[threadIdx.x + st];
        __syncthreads();
    }
    if (threadIdx.x == 0) dst[o] = b[o] + red[0];
}

// ------------------------------------------------------------------
// Chebyshev expansion (tanh.approx; 2 columns / thread)
// ------------------------------------------------------------------
__global__ void expand_x_kernel(const float* __restrict__ X) {
    long idx = (long)blockIdx.x * blockDim.x + threadIdx.x;   // over B*IN/2
    if (idx >= (long)B_DIM * IN_DIM / 2) return;
    int r  = (int)(idx / (IN_DIM / 2));
    int cp = (int)(idx % (IN_DIM / 2));
    float2 xv = reinterpret_cast<const float2*>(X)[idx];

    float t0 = tanh_fast(xv.x), t1 = tanh_fast(xv.y);
    float a2 = 2.f * t0 * t0 - 1.f,  b2 = 2.f * t1 * t1 - 1.f;
    float a3 = 2.f * t0 * a2 - t0,   b3 = 2.f * t1 * b2 - t1;
    float a4 = 2.f * t0 * a3 - a2,   b4 = 2.f * t1 * b3 - b2;

    __half* dst = g_Aexp + (size_t)r * K_TOT;
    reinterpret_cast<__half2*>(dst)[cp]              = __floats2half2_rn(xv.x, xv.y);
    reinterpret_cast<__half2*>(dst + IN_DIM)[cp]     = __floats2half2_rn(t0, t1);
    reinterpret_cast<__half2*>(dst + 2 * IN_DIM)[cp] = __floats2half2_rn(a2, b2);
    reinterpret_cast<__half2*>(dst + 3 * IN_DIM)[cp] = __floats2half2_rn(a3, b3);
    reinterpret_cast<__half2*>(dst + 4 * IN_DIM)[cp] = __floats2half2_rn(a4, b4);
}

__global__ void expand_h_kernel() {
    long idx = (long)blockIdx.x * blockDim.x + threadIdx.x;   // over B*H/2
    if (idx >= (long)B_DIM * H_DIM / 2) return;
    int r  = (int)(idx / (H_DIM / 2));
    int cp = (int)(idx % (H_DIM / 2));
    __half2 hv = reinterpret_cast<const __half2*>(g_H1h)[idx];
    float2 sc = reinterpret_cast<const float2*>(g_bnScale)[cp];
    float2 sh = reinterpret_cast<const float2*>(g_bnShift)[cp];
    float y0 = fmaf(sc.x, __half2float(hv.x), sh.x);
    float y1 = fmaf(sc.y, __half2float(hv.y), sh.y);

    float t0 = tanh_fast(y0), t1 = tanh_fast(y1);
    float a2 = 2.f * t0 * t0 - 1.f,  b2 = 2.f * t1 * t1 - 1.f;
    float a3 = 2.f * t0 * a2 - t0,   b3 = 2.f * t1 * b2 - t1;
    float a4 = 2.f * t0 * a3 - a2,   b4 = 2.f * t1 * b3 - b2;

    __half* dst = g_Aexp + (size_t)r * K_TOT;
    reinterpret_cast<__half2*>(dst)[cp]             = __floats2half2_rn(y0, y1);
    reinterpret_cast<__half2*>(dst + H_DIM)[cp]     = __floats2half2_rn(t0, t1);
    reinterpret_cast<__half2*>(dst + 2 * H_DIM)[cp] = __floats2half2_rn(a2, b2);
    reinterpret_cast<__half2*>(dst + 3 * H_DIM)[cp] = __floats2half2_rn(a3, b3);
    reinterpret_cast<__half2*>(dst + 4 * H_DIM)[cp] = __floats2half2_rn(a4, b4);
}

// ------------------------------------------------------------------
// BatchNorm statistics (deterministic 2-stage, half2 reads)
// ------------------------------------------------------------------
__global__ void bn_part_kernel() {   // grid (H/512, 32), block 256; 2 cols/thread
    int cp = blockIdx.x * 256 + threadIdx.x;
    int r0 = blockIdx.y * 256;
    float s0 = 0.f, s1 = 0.f, q0 = 0.f, q1 = 0.f;
    for (int r = 0; r < 256; ++r) {
        __half2 v = reinterpret_cast<const __half2*>(
            g_H1h + (size_t)(r0 + r) * H_DIM)[cp];
        float v0 = __half2float(v.x), v1 = __half2float(v.y);
        s0 += v0; s1 += v1;
        q0 += v0 * v0; q1 += v1 * v1;
    }
    reinterpret_cast<float2*>(g_partS  + blockIdx.y * H_DIM)[cp] = make_float2(s0, s1);
    reinterpret_cast<float2*>(g_partS2 + blockIdx.y * H_DIM)[cp] = make_float2(q0, q1);
}

__global__ void bn_fin_kernel(const float* __restrict__ gamma,
                              const float* __restrict__ beta) {
    int col = blockIdx.x * blockDim.x + threadIdx.x;
    if (col >= H_DIM) return;
    float s = 0.f, s2 = 0.f;
    for (int p = 0; p < 32; ++p) {
        s  += g_partS [p * H_DIM + col];
        s2 += g_partS2[p * H_DIM + col];
    }
    float invB = 1.f / (float)B_DIM;
    float mu  = s * invB;
    float var = s2 * invB - mu * mu;
    float inv = rsqrtf(var + BN_EPS);
    float sc  = gamma[col] * inv;
    g_bnScale[col] = sc;
    g_bnShift[col] = beta[col] - mu * sc;
}

// ------------------------------------------------------------------
// fp16 tensor-core GEMM: C = (A[M,K] * B[N,K]^T) * invScale + bias
// 128 x GBNT block tile, 8 warps, GBK=64, 4-stage cp.async,
// ldmatrix.x4 feeding, mma.m16n8k16 fp32 accum.
// ------------------------------------------------------------------
#define GBM 128
#define GBK 64
#define GSTAGES 4
#define LDP 72                                     // GBK + 8 pad
#define A_STG (GBM * LDP)

template <int GBNT, typename OutT>
__global__ void __launch_bounds__(256, 1)
gemm_fp16_kernel(const __half* __restrict__ A, const __half* __restrict__ B,
                 const float* __restrict__ bias, OutT* __restrict__ C,
                 int M, int N, int K) {
    constexpr int NI   = GBNT / 32;
    constexpr int WN   = GBNT / 4;
    constexpr int BSTG = GBNT * LDP;

    extern __shared__ __half smem[];
    __half* As = smem;
    __half* Bs = smem + GSTAGES * A_STG;

    const int tid  = threadIdx.x;
    const int lane = tid & 31;
    const int warp = tid >> 5;
    const int wm = warp >> 2;
    const int wn = warp & 3;

    const int bM = blockIdx.y * GBM;
    const int bN = blockIdx.x * GBNT;

    const __half* Ag = A + (size_t)bM * K;
    const __half* Bg = B + (size_t)bN * K;

    const int ldr = tid >> 3;
    const int ldc = (tid & 7) * 8;

    uint32_t asBase = (uint32_t)__cvta_generic_to_shared(As);
    uint32_t bsBase = (uint32_t)__cvta_generic_to_shared(Bs);

    auto loadTile = [&](int stage, int kt) {
        const __half* ga = Ag + (size_t)ldr * K + kt * GBK + ldc;
        const __half* gb = Bg + (size_t)ldr * K + kt * GBK + ldc;
        uint32_t sa  = asBase + (uint32_t)(((stage * GBM + ldr) * LDP + ldc) * 2);
        uint32_t sbp = bsBase + (uint32_t)(((stage * GBNT + ldr) * LDP + ldc) * 2);
#pragma unroll
        for (int i = 0; i < GBM / 32; ++i)
            asm volatile("cp.async.cg.shared.global [%0], [%1], 16;\n"
                         :: "r"(sa + i * 32 * LDP * 2), "l"(ga + (size_t)i * 32 * K));
#pragma unroll
        for (int i = 0; i < GBNT / 32; ++i)
            asm volatile("cp.async.cg.shared.global [%0], [%1], 16;\n"
                         :: "r"(sbp + i * 32 * LDP * 2), "l"(gb + (size_t)i * 32 * K));
    };

    float acc[4][NI][4];
#pragma unroll
    for (int mi = 0; mi < 4; ++mi)
#pragma unroll
        for (int ni = 0; ni < NI; ++ni)
#pragma unroll
            for (int r = 0; r < 4; ++r) acc[mi][ni][r] = 0.f;

    const int KT = K / GBK;
#pragma unroll
    for (int s = 0; s < GSTAGES - 1; ++s) {
        loadTile(s, s);
        asm volatile("cp.async.commit_group;\n");
    }

    const int jj = lane >> 3;
    const int lr = lane & 7;
    uint32_t aAddr[4];
#pragma unroll
    for (int mi = 0; mi < 4; ++mi) {
        int row = wm * 64 + mi * 16 + ((jj & 1) << 3) + lr;
        aAddr[mi] = asBase + (uint32_t)((row * LDP) * 2 + ((jj >> 1) << 4));
    }
    uint32_t bAddr[NI / 2];
#pragma unroll
    for (int p = 0; p < NI / 2; ++p) {
        int row = wn * WN + p * 16 + ((jj >> 1) << 3) + lr;
        bAddr[p] = bsBase + (uint32_t)((row * LDP) * 2 + ((jj & 1) << 4));
    }

    for (int kt = 0; kt < KT; ++kt) {
        asm volatile("cp.async.wait_group %0;\n" :: "n"(GSTAGES - 2));
        __syncthreads();
        int s = kt % GSTAGES;
        int nkt = kt + GSTAGES - 1;
        if (nkt < KT) loadTile(nkt % GSTAGES, nkt);
        asm volatile("cp.async.commit_group;\n");

        const uint32_t aStg = (uint32_t)(s * A_STG * 2);
        const uint32_t bStg = (uint32_t)(s * BSTG * 2);
#pragma unroll
        for (int kk = 0; kk < GBK / 16; ++kk) {
            const uint32_t kOff = kk * 32;
            uint32_t af[4][4], bf[NI][2];
#pragma unroll
            for (int mi = 0; mi < 4; ++mi)
                ldsm_x4(af[mi][0], af[mi][1], af[mi][2], af[mi][3],
                        aAddr[mi] + aStg + kOff);
#pragma unroll
            for (int p = 0; p < NI / 2; ++p)
                ldsm_x4(bf[2 * p][0], bf[2 * p][1], bf[2 * p + 1][0], bf[2 * p + 1][1],
                        bAddr[p] + bStg + kOff);
#pragma unroll
            for (int mi = 0; mi < 4; ++mi)
#pragma unroll
                for (int ni = 0; ni < NI; ++ni) {
                    asm volatile(
                        "mma.sync.aligned.m16n8k16.row.col.f32.f16.f16.f32 "
                        "{%0,%1,%2,%3}, {%4,%5,%6,%7}, {%8,%9}, {%0,%1,%2,%3};\n"
                        : "+f"(acc[mi][ni][0]), "+f"(acc[mi][ni][1]),
                          "+f"(acc[mi][ni][2]), "+f"(acc[mi][ni][3])
                        : "r"(af[mi][0]), "r"(af[mi][1]), "r"(af[mi][2]), "r"(af[mi][3]),
                          "r"(bf[ni][0]), "r"(bf[ni][1]));
                }
        }
    }

#pragma unroll
    for (int mi = 0; mi < 4; ++mi) {
        int r0 = bM + wm * 64 + mi * 16 + (lane >> 2);
#pragma unroll
        for (int ni = 0; ni < NI; ++ni) {
            int c = bN + wn * WN + ni * 8 + (lane & 3) * 2;
            float b0 = bias[c], b1v = bias[c + 1];
            float f00 = fmaf(acc[mi][ni][0], INV_WSCALE, b0);
            float f01 = fmaf(acc[mi][ni][1], INV_WSCALE, b1v);
            float f10 = fmaf(acc[mi][ni][2], INV_WSCALE, b0);
            float f11 = fmaf(acc[mi][ni][3], INV_WSCALE, b1v);
            if constexpr (sizeof(OutT) == 2) {
                *reinterpret_cast<__half2*>(&C[(size_t)r0 * N + c]) =
                    __floats2half2_rn(f00, f01);
                *reinterpret_cast<__half2*>(&C[(size_t)(r0 + 8) * N + c]) =
                    __floats2half2_rn(f10, f11);
            } else {
                *reinterpret_cast<float2*>(&C[(size_t)r0 * N + c]) =
                    make_float2(f00, f01);
                *reinterpret_cast<float2*>(&C[(size_t)(r0 + 8) * N + c]) =
                    make_float2(f10, f11);
            }
        }
    }
}

#define SMEM1 (GSTAGES * (A_STG + 256 * LDP) * 2)   // 221184
#define SMEM2 (GSTAGES * (A_STG + 128 * LDP) * 2)   // 147456

// ------------------------------------------------------------------
// launch
// ------------------------------------------------------------------
extern "C" void kernel_launch(void* const* d_in, const int* in_sizes, int n_in,
                              void* d_out, int out_size) {
    const float* x     = (const float*)d_in[0];
    const float* w1    = (const float*)d_in[1];
    const float* b1    = (const float*)d_in[2];
    const float* c1    = (const float*)d_in[3];
    const float* s1    = (const float*)d_in[4];
    const float* gamma = (const float*)d_in[5];
    const float* beta  = (const float*)d_in[6];
    const float* w2    = (const float*)d_in[7];
    const float* b2    = (const float*)d_in[8];
    const float* c2    = (const float*)d_in[9];
    const float* s2    = (const float*)d_in[10];
    float* out = (float*)d_out;

    cudaFuncSetAttribute(gemm_fp16_kernel<256, __half>,
                         cudaFuncAttributeMaxDynamicSharedMemorySize, SMEM1);
    cudaFuncSetAttribute(gemm_fp16_kernel<128, float>,
                         cudaFuncAttributeMaxDynamicSharedMemorySize, SMEM2);

    void *pA, *pW1, *pW2, *pH1, *pB1, *pB2, *pC1d0, *pC2d0;
    cudaGetSymbolAddress(&pA,    g_Aexp);
    cudaGetSymbolAddress(&pW1,   g_W1f);
    cudaGetSymbolAddress(&pW2,   g_W2f);
    cudaGetSymbolAddress(&pH1,   g_H1h);
    cudaGetSymbolAddress(&pB1,   g_bias1);
    cudaGetSymbolAddress(&pB2,   g_bias2);
    cudaGetSymbolAddress(&pC1d0, g_c1d0);
    cudaGetSymbolAddress(&pC2d0, g_c2d0);

    // ---- weight fusion (transpose) + base blocks + biases ----
    {
        dim3 g1(IN_DIM / 32, H_DIM / 32);
        fuse_c_kernel<<<g1, 256>>>(c1, s1, (__half*)pW1, (float*)pC1d0, IN_DIM, H_DIM);
        dim3 g2(H_DIM / 32, OUT_DIM / 32);
        fuse_c_kernel<<<g2, 256>>>(c2, s2, (__half*)pW2, (float*)pC2d0, H_DIM, OUT_DIM);
    }
    base_w_kernel<<<((long)H_DIM * IN_DIM + 255) / 256, 256>>>(
        w1, (__half*)pW1, IN_DIM, (long)H_DIM * IN_DIM);
    base_w_kernel<<<((long)OUT_DIM * H_DIM + 255) / 256, 256>>>(
        w2, (__half*)pW2, H_DIM, (long)OUT_DIM * H_DIM);
    bias_reduce_kernel<<<H_DIM, 256>>>((const float*)pC1d0, b1, (float*)pB1, IN_DIM);
    bias_reduce_kernel<<<OUT_DIM, 256>>>((const float*)pC2d0, b2, (float*)pB2, H_DIM);

    // ---- layer 1 ----
    expand_x_kernel<<<(B_DIM * IN_DIM / 2 + 255) / 256, 256>>>(x);
    {
        dim3 grid(H_DIM / 256, B_DIM / GBM);   // (8, 64)
        gemm_fp16_kernel<256, __half><<<grid, 256, SMEM1>>>(
            (const __half*)pA, (const __half*)pW1, (const float*)pB1,
            (__half*)pH1, B_DIM, H_DIM, K_TOT);
    }

    // ---- batchnorm stats ----
    bn_part_kernel<<<dim3(H_DIM / 512, 32), 256>>>();
    bn_fin_kernel<<<H_DIM / 256, 256>>>(gamma, beta);

    // ---- layer 2 ----
    expand_h_kernel<<<(B_DIM * H_DIM / 2 + 255) / 256, 256>>>();
    {
        dim3 grid(OUT_DIM / 128, B_DIM / GBM); // (4, 64)
        gemm_fp16_kernel<128, float><<<grid, 256, SMEM2>>>(
            (const __half*)pA, (const __half*)pW2, (const float*)pB2,
            out, B_DIM, OUT_DIM, K_TOT);
    }
}

// round 8
// speedup vs baseline: 1.1835x; 1.1835x over previous
#include <cuda_runtime.h>
#include <cuda_fp16.h>
#include <cstdint>
#include <cstdio>

// ------------------------------------------------------------------
// Problem constants
// ------------------------------------------------------------------
#define B_DIM   8192
#define IN_DIM  2048
#define H_DIM   2048
#define OUT_DIM 512
#define DEGP1   5
#define K_TOT (IN_DIM * DEGP1)   // 10240 (both layers)
#define BN_EPS 1e-5f
#define WSCALE 256.0f
#define INV_WSCALE (1.0f / 256.0f)

// ------------------------------------------------------------------
// Scratch (device globals; no runtime allocation)
// ------------------------------------------------------------------
__device__ __half g_Aexp[(size_t)B_DIM * K_TOT];    // expanded activations (fp16)
__device__ __half g_W1f [(size_t)H_DIM * K_TOT];    // fused W1 (fp16, x256)
__device__ __half g_W2f [(size_t)OUT_DIM * K_TOT];  // fused W2 (fp16, x256)
__device__ __half g_H1h [(size_t)B_DIM * H_DIM];    // layer-1 pre-BN output (fp16)
__device__ float  g_c1d0[(size_t)H_DIM * IN_DIM];   // s1[h]*c1[i,h,0], transposed
__device__ float  g_c2d0[(size_t)OUT_DIM * H_DIM];
__device__ float  g_bias1[H_DIM];
__device__ float  g_bias2[OUT_DIM];
__device__ float  g_partS [32 * H_DIM];
__device__ float  g_partS2[32 * H_DIM];
__device__ float  g_bnScale[H_DIM];
__device__ float  g_bnShift[H_DIM];

// ------------------------------------------------------------------
// helpers
// ------------------------------------------------------------------
__device__ __forceinline__ void ldsm_x4(uint32_t& r0, uint32_t& r1,
                                        uint32_t& r2, uint32_t& r3, uint32_t addr) {
    asm volatile("ldmatrix.sync.aligned.m8n8.x4.shared.b16 {%0,%1,%2,%3}, [%4];"
                 : "=r"(r0), "=r"(r1), "=r"(r2), "=r"(r3) : "r"(addr));
}

__device__ __forceinline__ float tanh_fast(float x) {
    float r;
    asm("tanh.approx.f32 %0, %1;" : "=f"(r) : "f"(x));
    return r;
}

// ------------------------------------------------------------------
// Coefficient fusion via smem transpose.
// ------------------------------------------------------------------
__global__ void fuse_c_kernel(const float* __restrict__ c,
                              const float* __restrict__ s,
                              __half* __restrict__ Wf,
                              float* __restrict__ cd0,
                              int In, int Hh) {
    __shared__ float sm[160][33];
    const int tid = threadIdx.x;
    const int i0 = blockIdx.x * 32;
    const int h0 = blockIdx.y * 32;

    for (int e = tid; e < 32 * 160; e += 256) {
        int ii  = e / 160;
        int pos = e % 160;
        sm[pos][ii] = c[(size_t)(i0 + ii) * Hh * DEGP1 + (size_t)h0 * DEGP1 + pos];
    }
    __syncthreads();

    const int lane = tid & 31;
    for (int hl = tid >> 5; hl < 32; hl += 8) {
        float sv = s[h0 + hl];
        cd0[(size_t)(h0 + hl) * In + i0 + lane] = sv * sm[hl * DEGP1][lane];
        __half* wrow = Wf + (size_t)(h0 + hl) * (In * DEGP1);
#pragma unroll
        for (int d = 1; d < DEGP1; ++d)
            wrow[d * In + i0 + lane] =
                __float2half_rn(WSCALE * sv * sm[hl * DEGP1 + d][lane]);
    }
}

// W base block (d=0): Wf[row][col] = half(WSCALE * w[row][col])
__global__ void base_w_kernel(const float* __restrict__ w,
                              __half* __restrict__ Wf, int In, long total) {
    long idx = (long)blockIdx.x * blockDim.x + threadIdx.x;
    if (idx >= total) return;
    int row = (int)(idx / In);
    int col = (int)(idx % In);
    Wf[(size_t)row * (In * DEGP1) + col] = __float2half_rn(WSCALE * w[idx]);
}

// bias[o] = b[o] + sum_j staged[o*len + j]
__global__ void bias_reduce_kernel(const float* __restrict__ staged,
                                   const float* __restrict__ b,
                                   float* __restrict__ dst, int len) {
    __shared__ float red[256];
    int o = blockIdx.x;
    const float* src = staged + (size_t)o * len;
    float s = 0.f;
    for (int j = threadIdx.x; j < len; j += 256) s += src[j];
    red[threadIdx.x] = s;
    __syncthreads();
    for (int st = 128; st > 0; st >>= 1) {
        if (threadIdx.x < st) red[threadIdx.x] += red[threadIdx.x + st];
        __syncthreads();
    }
    if (threadIdx.x == 0) dst[o] = b[o] + red[0];
}

// ------------------------------------------------------------------
// Chebyshev expansion
// ------------------------------------------------------------------
__global__ void expand_x_kernel(const float* __restrict__ X) {
    long idx = (long)blockIdx.x * blockDim.x + threadIdx.x;
    if (idx >= (long)B_DIM * IN_DIM / 2) return;
    int r  = (int)(idx / (IN_DIM / 2));
    int cp = (int)(idx % (IN_DIM / 2));
    float2 xv = reinterpret_cast<const float2*>(X)[idx];

    float t0 = tanh_fast(xv.x), t1 = tanh_fast(xv.y);
    float a2 = 2.f * t0 * t0 - 1.f,  b2 = 2.f * t1 * t1 - 1.f;
    float a3 = 2.f * t0 * a2 - t0,   b3 = 2.f * t1 * b2 - t1;
    float a4 = 2.f * t0 * a3 - a2,   b4 = 2.f * t1 * b3 - b2;

    __half* dst = g_Aexp + (size_t)r * K_TOT;
    reinterpret_cast<__half2*>(dst)[cp]              = __floats2half2_rn(xv.x, xv.y);
    reinterpret_cast<__half2*>(dst + IN_DIM)[cp]     = __floats2half2_rn(t0, t1);
    reinterpret_cast<__half2*>(dst + 2 * IN_DIM)[cp] = __floats2half2_rn(a2, b2);
    reinterpret_cast<__half2*>(dst + 3 * IN_DIM)[cp] = __floats2half2_rn(a3, b3);
    reinterpret_cast<__half2*>(dst + 4 * IN_DIM)[cp] = __floats2half2_rn(a4, b4);
}

__global__ void expand_h_kernel() {
    long idx = (long)blockIdx.x * blockDim.x + threadIdx.x;
    if (idx >= (long)B_DIM * H_DIM / 2) return;
    int r  = (int)(idx / (H_DIM / 2));
    int cp = (int)(idx % (H_DIM / 2));
    __half2 hv = reinterpret_cast<const __half2*>(g_H1h)[idx];
    float2 sc = reinterpret_cast<const float2*>(g_bnScale)[cp];
    float2 sh = reinterpret_cast<const float2*>(g_bnShift)[cp];
    float y0 = fmaf(sc.x, __half2float(hv.x), sh.x);
    float y1 = fmaf(sc.y, __half2float(hv.y), sh.y);

    float t0 = tanh_fast(y0), t1 = tanh_fast(y1);
    float a2 = 2.f * t0 * t0 - 1.f,  b2 = 2.f * t1 * t1 - 1.f;
    float a3 = 2.f * t0 * a2 - t0,   b3 = 2.f * t1 * b2 - t1;
    float a4 = 2.f * t0 * a3 - a2,   b4 = 2.f * t1 * b3 - b2;

    __half* dst = g_Aexp + (size_t)r * K_TOT;
    reinterpret_cast<__half2*>(dst)[cp]             = __floats2half2_rn(y0, y1);
    reinterpret_cast<__half2*>(dst + H_DIM)[cp]     = __floats2half2_rn(t0, t1);
    reinterpret_cast<__half2*>(dst + 2 * H_DIM)[cp] = __floats2half2_rn(a2, b2);
    reinterpret_cast<__half2*>(dst + 3 * H_DIM)[cp] = __floats2half2_rn(a3, b3);
    reinterpret_cast<__half2*>(dst + 4 * H_DIM)[cp] = __floats2half2_rn(a4, b4);
}

// ------------------------------------------------------------------
// BatchNorm statistics (deterministic 2-stage, half2 reads)
// ------------------------------------------------------------------
__global__ void bn_part_kernel() {
    int cp = blockIdx.x * 256 + threadIdx.x;
    int r0 = blockIdx.y * 256;
    float s0 = 0.f, s1 = 0.f, q0 = 0.f, q1 = 0.f;
    for (int r = 0; r < 256; ++r) {
        __half2 v = reinterpret_cast<const __half2*>(
            g_H1h + (size_t)(r0 + r) * H_DIM)[cp];
        float v0 = __half2float(v.x), v1 = __half2float(v.y);
        s0 += v0; s1 += v1;
        q0 += v0 * v0; q1 += v1 * v1;
    }
    reinterpret_cast<float2*>(g_partS  + blockIdx.y * H_DIM)[cp] = make_float2(s0, s1);
    reinterpret_cast<float2*>(g_partS2 + blockIdx.y * H_DIM)[cp] = make_float2(q0, q1);
}

__global__ void bn_fin_kernel(const float* __restrict__ gamma,
                              const float* __restrict__ beta) {
    int col = blockIdx.x * blockDim.x + threadIdx.x;
    if (col >= H_DIM) return;
    float s = 0.f, s2 = 0.f;
    for (int p = 0; p < 32; ++p) {
        s  += g_partS [p * H_DIM + col];
        s2 += g_partS2[p * H_DIM + col];
    }
    float invB = 1.f / (float)B_DIM;
    float mu  = s * invB;
    float var = s2 * invB - mu * mu;
    float inv = rsqrtf(var + BN_EPS);
    float sc  = gamma[col] * inv;
    g_bnScale[col] = sc;
    g_bnShift[col] = beta[col] - mu * sc;
}

// ------------------------------------------------------------------
// fp16 tensor-core GEMM: C = (A[M,K] * B[N,K]^T) * invScale + bias
// 128x128 block tile, 8 warps (warp tile 64x32), GBK=64, 3-stage
// cp.async pipeline, ldmatrix.x4 feeding, mma.m16n8k16 fp32 accum.
// 110.6 KB smem/CTA -> 2 CTAs/SM (16 warps) to hide pipe stalls.
// ------------------------------------------------------------------
#define GBM 128
#define GBN 128
#define GBK 64
#define GSTAGES 3
#define LDP 72                                     // GBK + 8 pad
#define A_STG (GBM * LDP)
#define B_STG (GBN * LDP)
#define GEMM_SMEM (GSTAGES * (A_STG + B_STG) * 2)  // 110592 B

template <typename OutT>
__global__ void __launch_bounds__(256, 2)
gemm_fp16_kernel(const __half* __restrict__ A, const __half* __restrict__ B,
                 const float* __restrict__ bias, OutT* __restrict__ C,
                 int M, int N, int K) {
    constexpr int NI = 4;     // 4 n-tiles (8 wide) per warp
    constexpr int WN = 32;    // warp n extent

    extern __shared__ __half smem[];
    __half* As = smem;
    __half* Bs = smem + GSTAGES * A_STG;

    const int tid  = threadIdx.x;
    const int lane = tid & 31;
    const int warp = tid >> 5;
    const int wm = warp >> 2;     // 0..1 (64-row tiles)
    const int wn = warp & 3;      // 0..3 (32-col tiles)

    const int bM = blockIdx.y * GBM;
    const int bN = blockIdx.x * GBN;

    const __half* Ag = A + (size_t)bM * K;
    const __half* Bg = B + (size_t)bN * K;

    const int ldr = tid >> 3;
    const int ldc = (tid & 7) * 8;

    uint32_t asBase = (uint32_t)__cvta_generic_to_shared(As);
    uint32_t bsBase = (uint32_t)__cvta_generic_to_shared(Bs);

    auto loadTile = [&](int stage, int kt) {
        const __half* ga = Ag + (size_t)ldr * K + kt * GBK + ldc;
        const __half* gb = Bg + (size_t)ldr * K + kt * GBK + ldc;
        uint32_t sa  = asBase + (uint32_t)(((stage * GBM + ldr) * LDP + ldc) * 2);
        uint32_t sbp = bsBase + (uint32_t)(((stage * GBN + ldr) * LDP + ldc) * 2);
#pragma unroll
        for (int i = 0; i < 4; ++i)
            asm volatile("cp.async.cg.shared.global [%0], [%1], 16;\n"
                         :: "r"(sa + i * 32 * LDP * 2), "l"(ga + (size_t)i * 32 * K));
#pragma unroll
        for (int i = 0; i < 4; ++i)
            asm volatile("cp.async.cg.shared.global [%0], [%1], 16;\n"
                         :: "r"(sbp + i * 32 * LDP * 2), "l"(gb + (size_t)i * 32 * K));
    };

    float acc[4][NI][4];
#pragma unroll
    for (int mi = 0; mi < 4; ++mi)
#pragma unroll
        for (int ni = 0; ni < NI; ++ni)
#pragma unroll
            for (int r = 0; r < 4; ++r) acc[mi][ni][r] = 0.f;

    const int KT = K / GBK;
#pragma unroll
    for (int s = 0; s < GSTAGES - 1; ++s) {
        loadTile(s, s);
        asm volatile("cp.async.commit_group;\n");
    }

    const int jj = lane >> 3;
    const int lr = lane & 7;
    uint32_t aAddr[4];
#pragma unroll
    for (int mi = 0; mi < 4; ++mi) {
        int row = wm * 64 + mi * 16 + ((jj & 1) << 3) + lr;
        aAddr[mi] = asBase + (uint32_t)((row * LDP) * 2 + ((jj >> 1) << 4));
    }
    uint32_t bAddr[NI / 2];
#pragma unroll
    for (int p = 0; p < NI / 2; ++p) {
        int row = wn * WN + p * 16 + ((jj >> 1) << 3) + lr;
        bAddr[p] = bsBase + (uint32_t)((row * LDP) * 2 + ((jj & 1) << 4));
    }

    for (int kt = 0; kt < KT; ++kt) {
        asm volatile("cp.async.wait_group %0;\n" :: "n"(GSTAGES - 2));
        __syncthreads();
        int s = kt % GSTAGES;
        int nkt = kt + GSTAGES - 1;
        if (nkt < KT) loadTile(nkt % GSTAGES, nkt);
        asm volatile("cp.async.commit_group;\n");

        const uint32_t aStg = (uint32_t)(s * A_STG * 2);
        const uint32_t bStg = (uint32_t)(s * B_STG * 2);
#pragma unroll
        for (int kk = 0; kk < GBK / 16; ++kk) {
            const uint32_t kOff = kk * 32;
            uint32_t af[4][4], bf[NI][2];
#pragma unroll
            for (int mi = 0; mi < 4; ++mi)
                ldsm_x4(af[mi][0], af[mi][1], af[mi][2], af[mi][3],
                        aAddr[mi] + aStg + kOff);
#pragma unroll
            for (int p = 0; p < NI / 2; ++p)
                ldsm_x4(bf[2 * p][0], bf[2 * p][1], bf[2 * p + 1][0], bf[2 * p + 1][1],
                        bAddr[p] + bStg + kOff);
#pragma unroll
            for (int mi = 0; mi < 4; ++mi)
#pragma unroll
                for (int ni = 0; ni < NI; ++ni) {
                    asm volatile(
                        "mma.sync.aligned.m16n8k16.row.col.f32.f16.f16.f32 "
                        "{%0,%1,%2,%3}, {%4,%5,%6,%7}, {%8,%9}, {%0,%1,%2,%3};\n"
                        : "+f"(acc[mi][ni][0]), "+f"(acc[mi][ni][1]),
                          "+f"(acc[mi][ni][2]), "+f"(acc[mi][ni][3])
                        : "r"(af[mi][0]), "r"(af[mi][1]), "r"(af[mi][2]), "r"(af[mi][3]),
                          "r"(bf[ni][0]), "r"(bf[ni][1]));
                }
        }
    }

#pragma unroll
    for (int mi = 0; mi < 4; ++mi) {
        int r0 = bM + wm * 64 + mi * 16 + (lane >> 2);
#pragma unroll
        for (int ni = 0; ni < NI; ++ni) {
            int c = bN + wn * WN + ni * 8 + (lane & 3) * 2;
            float b0 = bias[c], b1v = bias[c + 1];
            float f00 = fmaf(acc[mi][ni][0], INV_WSCALE, b0);
            float f01 = fmaf(acc[mi][ni][1], INV_WSCALE, b1v);
            float f10 = fmaf(acc[mi][ni][2], INV_WSCALE, b0);
            float f11 = fmaf(acc[mi][ni][3], INV_WSCALE, b1v);
            if constexpr (sizeof(OutT) == 2) {
                *reinterpret_cast<__half2*>(&C[(size_t)r0 * N + c]) =
                    __floats2half2_rn(f00, f01);
                *reinterpret_cast<__half2*>(&C[(size_t)(r0 + 8) * N + c]) =
                    __floats2half2_rn(f10, f11);
            } else {
                *reinterpret_cast<float2*>(&C[(size_t)r0 * N + c]) =
                    make_float2(f00, f01);
                *reinterpret_cast<float2*>(&C[(size_t)(r0 + 8) * N + c]) =
                    make_float2(f10, f11);
            }
        }
    }
}

// ------------------------------------------------------------------
// launch  (GEMM1 placed at launch #5 so ncu's fixed -s window hits it)
// ------------------------------------------------------------------
extern "C" void kernel_launch(void* const* d_in, const int* in_sizes, int n_in,
                              void* d_out, int out_size) {
    const float* x     = (const float*)d_in[0];
    const float* w1    = (const float*)d_in[1];
    const float* b1    = (const float*)d_in[2];
    const float* c1    = (const float*)d_in[3];
    const float* s1    = (const float*)d_in[4];
    const float* gamma = (const float*)d_in[5];
    const float* beta  = (const float*)d_in[6];
    const float* w2    = (const float*)d_in[7];
    const float* b2    = (const float*)d_in[8];
    const float* c2    = (const float*)d_in[9];
    const float* s2    = (const float*)d_in[10];
    float* out = (float*)d_out;

    cudaFuncSetAttribute(gemm_fp16_kernel<__half>,
                         cudaFuncAttributeMaxDynamicSharedMemorySize, GEMM_SMEM);
    cudaFuncSetAttribute(gemm_fp16_kernel<float>,
                         cudaFuncAttributeMaxDynamicSharedMemorySize, GEMM_SMEM);

    void *pA, *pW1, *pW2, *pH1, *pB1, *pB2, *pC1d0, *pC2d0;
    cudaGetSymbolAddress(&pA,    g_Aexp);
    cudaGetSymbolAddress(&pW1,   g_W1f);
    cudaGetSymbolAddress(&pW2,   g_W2f);
    cudaGetSymbolAddress(&pH1,   g_H1h);
    cudaGetSymbolAddress(&pB1,   g_bias1);
    cudaGetSymbolAddress(&pB2,   g_bias2);
    cudaGetSymbolAddress(&pC1d0, g_c1d0);
    cudaGetSymbolAddress(&pC2d0, g_c2d0);

    // ---- layer-1 prep (4 launches), then GEMM1 at launch #5 ----
    {
        dim3 g1(IN_DIM / 32, H_DIM / 32);
        fuse_c_kernel<<<g1, 256>>>(c1, s1, (__half*)pW1, (float*)pC1d0, IN_DIM, H_DIM);
    }
    base_w_kernel<<<((long)H_DIM * IN_DIM + 255) / 256, 256>>>(
        w1, (__half*)pW1, IN_DIM, (long)H_DIM * IN_DIM);
    bias_reduce_kernel<<<H_DIM, 256>>>((const float*)pC1d0, b1, (float*)pB1, IN_DIM);
    expand_x_kernel<<<(B_DIM * IN_DIM / 2 + 255) / 256, 256>>>(x);
    {
        dim3 grid(H_DIM / GBN, B_DIM / GBM);   // (16, 64)
        gemm_fp16_kernel<__half><<<grid, 256, GEMM_SMEM>>>(
            (const __half*)pA, (const __half*)pW1, (const float*)pB1,
            (__half*)pH1, B_DIM, H_DIM, K_TOT);
    }

    // ---- layer-2 weight prep (independent of GEMM1 results) ----
    {
        dim3 g2(H_DIM / 32, OUT_DIM / 32);
        fuse_c_kernel<<<g2, 256>>>(c2, s2, (__half*)pW2, (float*)pC2d0, H_DIM, OUT_DIM);
    }
    base_w_kernel<<<((long)OUT_DIM * H_DIM + 255) / 256, 256>>>(
        w2, (__half*)pW2, H_DIM, (long)OUT_DIM * H_DIM);
    bias_reduce_kernel<<<OUT_DIM, 256>>>((const float*)pC2d0, b2, (float*)pB2, H_DIM);

    // ---- batchnorm stats ----
    bn_part_kernel<<<dim3(H_DIM / 512, 32), 256>>>();
    bn_fin_kernel<<<H_DIM / 256, 256>>>(gamma, beta);

    // ---- layer 2 ----
    expand_h_kernel<<<(B_DIM * H_DIM / 2 + 255) / 256, 256>>>();
    {
        dim3 grid(OUT_DIM / GBN, B_DIM / GBM); // (4, 64)
        gemm_fp16_kernel<float><<<grid, 256, GEMM_SMEM>>>(
            (const __half*)pA, (const __half*)pW2, (const float*)pB2,
            out, B_DIM, OUT_DIM, K_TOT);
    }
}